// round 1
// baseline (speedup 1.0000x reference)
#include <cuda_runtime.h>
#include <math_constants.h>

// Problem constants: x [B=32, C=256, H=64, W=64] fp32
#define B   32
#define C   256
#define HW  4096          // 64*64
#define W64 64

// ---- Kernel 1 config: fused reduction pass over x ----
// 128 threads/block, each thread owns one float4 (4 hw positions).
// Block tile = 512 hw positions; grid = B * (HW/512) = 256 blocks.
#define K1_THREADS 128
#define K1_TILE    512
#define K1_TILES   (HW / K1_TILE)   // 8
#define K1_WARPS   (K1_THREADS / 32) // 4

// ---- Scratch (device globals; allocation-free contract) ----
__device__ float  g_csum_part[B * K1_TILES * K1_WARPS * C]; // per-(b,c) partial HW-sums
__device__ float4 g_hwmax4[B * HW / 4];   // max over C, per (b,hw)
__device__ float4 g_hwsum4[B * HW / 4];   // sum over C, per (b,hw)
__device__ float  g_chw[B * C];           // sigmoid(conv1d(mean))  (channel weight)
__device__ float4 g_sp4[B * HW / 4];      // sigmoid(conv2d(pools)) (spatial weight)

// =====================================================================
// Kernel 1: one sweep over x.
//   - per-(b,c) sum over the block's 512 hw positions -> warp partials
//   - per-(b,hw) running max & sum over all 256 channels -> direct store
// =====================================================================
__global__ __launch_bounds__(K1_THREADS) void k1_reduce(const float* __restrict__ x)
{
    const int bid  = blockIdx.x;
    const int b    = bid / K1_TILES;
    const int tile = bid % K1_TILES;
    const int tid  = threadIdx.x;
    const int warp = tid >> 5;
    const int lane = tid & 31;

    const int hwbase = tile * K1_TILE + tid * 4;
    const float4* __restrict__ xp =
        (const float4*)(x + (long)b * C * HW + hwbase);   // stride between c = HW/4 float4

    float4 mx = make_float4(-CUDART_INF_F, -CUDART_INF_F, -CUDART_INF_F, -CUDART_INF_F);
    float4 sm = make_float4(0.f, 0.f, 0.f, 0.f);

    float* __restrict__ part =
        &g_csum_part[((b * K1_TILES + tile) * K1_WARPS + warp) * C];

    #pragma unroll 8
    for (int c = 0; c < C; ++c) {
        float4 v = xp[c * (HW / 4)];
        mx.x = fmaxf(mx.x, v.x); mx.y = fmaxf(mx.y, v.y);
        mx.z = fmaxf(mx.z, v.z); mx.w = fmaxf(mx.w, v.w);
        sm.x += v.x; sm.y += v.y; sm.z += v.z; sm.w += v.w;

        // per-c partial sum across this warp's 128 hw positions
        float s = (v.x + v.y) + (v.z + v.w);
        s += __shfl_xor_sync(0xffffffffu, s, 16);
        s += __shfl_xor_sync(0xffffffffu, s, 8);
        s += __shfl_xor_sync(0xffffffffu, s, 4);
        s += __shfl_xor_sync(0xffffffffu, s, 2);
        s += __shfl_xor_sync(0xffffffffu, s, 1);
        if (lane == 0) part[c] = s;
    }

    const int o4 = (b * HW + hwbase) >> 2;   // float4 index
    g_hwmax4[o4] = mx;
    g_hwsum4[o4] = sm;
}

// =====================================================================
// Kernel 2: finish per-(b,c) mean, 5-tap conv1d along c (zero pad 2),
//           sigmoid -> g_chw.  grid = B, threads = C.
// =====================================================================
__global__ __launch_bounds__(C) void k2_chw(const float* __restrict__ w1d)
{
    const int b = blockIdx.x;
    const int c = threadIdx.x;

    float acc = 0.f;
    #pragma unroll
    for (int t = 0; t < K1_TILES * K1_WARPS; ++t)
        acc += g_csum_part[(b * K1_TILES * K1_WARPS + t) * C + c];

    __shared__ float mean[C];
    mean[c] = acc * (1.0f / (float)HW);
    __syncthreads();

    float y = 0.f;
    #pragma unroll
    for (int k = 0; k < 5; ++k) {
        int cc = c - 2 + k;
        float m = (cc >= 0 && cc < C) ? mean[cc] : 0.f;
        y += w1d[k] * m;
    }
    g_chw[b * C + c] = 1.0f / (1.0f + expf(-y));
}

// =====================================================================
// Kernel 3: spatial attention. 7x7 conv over [max_pool, avg_pool] with
//           zero pad 3, + bias, sigmoid -> g_sp.
// Block handles (b, 16-row tile). grid = B*4, 256 threads.
// =====================================================================
#define K3_ROWS 16
__global__ __launch_bounds__(256) void k3_sp(const float* __restrict__ w2d,
                                             const float* __restrict__ bias)
{
    const int b  = blockIdx.x >> 2;
    const int rt = blockIdx.x & 3;
    const int r0 = rt * K3_ROWS;
    const int tid = threadIdx.x;

    __shared__ float smax[22][72];   // rows r0-3 .. r0+18, cols -3..66
    __shared__ float savg[22][72];
    __shared__ float sw[98];
    __shared__ float sb;

    const float* __restrict__ gm = (const float*)g_hwmax4;
    const float* __restrict__ gs = (const float*)g_hwsum4;

    for (int i = tid; i < 22 * 70; i += 256) {
        int rr = i / 70, cc = i % 70;
        int gr = r0 - 3 + rr, gc = cc - 3;
        float mv = 0.f, av = 0.f;
        if (gr >= 0 && gr < W64 && gc >= 0 && gc < W64) {
            int idx = b * HW + gr * W64 + gc;
            mv = gm[idx];
            av = gs[idx] * (1.0f / (float)C);
        }
        smax[rr][cc] = mv;
        savg[rr][cc] = av;
    }
    if (tid < 98) sw[tid] = w2d[tid];
    if (tid == 0) sb = bias[0];
    __syncthreads();

    float* __restrict__ sp = (float*)g_sp4;
    #pragma unroll
    for (int k = 0; k < 4; ++k) {
        int oi   = tid + k * 256;         // 0..1023
        int orow = oi >> 6;               // 0..15
        int ocol = oi & 63;
        float acc = sb;
        #pragma unroll
        for (int kh = 0; kh < 7; ++kh) {
            #pragma unroll
            for (int kw = 0; kw < 7; ++kw) {
                acc += sw[kh * 7 + kw]      * smax[orow + kh][ocol + kw];
                acc += sw[49 + kh * 7 + kw] * savg[orow + kh][ocol + kw];
            }
        }
        sp[b * HW + (r0 + orow) * W64 + ocol] = 1.0f / (1.0f + expf(-acc));
    }
}

// =====================================================================
// Kernel 4: out = x * (chw[b,c] + sp[b,hw] + 1)   (float4 streaming)
// =====================================================================
__global__ __launch_bounds__(256) void k4_scale(const float4* __restrict__ x4,
                                                float4* __restrict__ out4)
{
    const int i4  = blockIdx.x * 256 + threadIdx.x;  // < B*C*HW/4 = 8388608
    const int hw4 = i4 & 1023;                       // HW/4 = 1024
    const int bc  = i4 >> 10;                        // b*C + c
    const int b   = bc >> 8;

    const float cw = g_chw[bc] + 1.0f;
    const float4 sp = g_sp4[b * 1024 + hw4];
    const float4 v  = x4[i4];

    float4 o;
    o.x = v.x * (cw + sp.x);
    o.y = v.y * (cw + sp.y);
    o.z = v.z * (cw + sp.z);
    o.w = v.w * (cw + sp.w);
    out4[i4] = o;
}

// =====================================================================
extern "C" void kernel_launch(void* const* d_in, const int* in_sizes, int n_in,
                              void* d_out, int out_size)
{
    const float* x    = (const float*)d_in[0];  // [32,256,64,64]
    const float* w1d  = (const float*)d_in[1];  // [1,1,5]
    const float* w2d  = (const float*)d_in[2];  // [1,2,7,7]
    const float* bias = (const float*)d_in[3];  // [1]
    float* out = (float*)d_out;

    k1_reduce<<<B * K1_TILES, K1_THREADS>>>(x);
    k2_chw<<<B, C>>>(w1d);
    k3_sp<<<B * 4, 256>>>(w2d, bias);
    k4_scale<<<(B * C * HW / 4) / 256, 256>>>((const float4*)x, (float4*)out);
}

// round 2
// speedup vs baseline: 1.6340x; 1.6340x over previous
#include <cuda_runtime.h>
#include <math_constants.h>

// x [B=32, C=256, H=64, W=64] fp32
#define B    32
#define C    256
#define HW   4096
#define W64  64

// ---- k1 tiling ----
#define K1T   256              // threads/block
#define HWT   1024             // hw floats per block tile (256 float4)
#define NHWT  (HW / HWT)       // 4
#define CR    64               // channels per block
#define NCR   (C / CR)         // 4

// ---- scratch (device globals; allocation-free contract) ----
__device__ float  g_cpart[B * NHWT * C];        // per-(b,c) hw-tile partial sums
__device__ float4 g_pmax[NCR][B * HW / 4];      // per-c-range max partials
__device__ float4 g_psum[NCR][B * HW / 4];      // per-c-range sum partials
__device__ float  g_chw[B * C];                 // sigmoid(conv1d(mean)) channel weight
__device__ float4 g_sp4[B * HW / 4];            // sigmoid(conv2d(pools)) spatial weight

// =====================================================================
// k1: single sweep over x with high occupancy.
//   block = (b, hw-tile of 1024, c-range of 64), grid = 32*4*4 = 512
//   - per-(b,hw) max/sum over its 64 channels -> register partials
//   - per-(b,c) sums via smem transpose amortized over 8 channels
// =====================================================================
__global__ __launch_bounds__(K1T) void k1_reduce(const float* __restrict__ x)
{
    const int b    = blockIdx.z;
    const int ht   = blockIdx.y;
    const int cr   = blockIdx.x;
    const int tid  = threadIdx.x;
    const int warp = tid >> 5;
    const int lane = tid & 31;

    __shared__ float sbuf[2][8][K1T];   // double-buffered transpose staging

    const float4* __restrict__ xp =
        (const float4*)x + ((long)(b * C + cr * CR) * HW + ht * HWT) / 4 + tid;

    float4 mx = make_float4(-CUDART_INF_F, -CUDART_INF_F, -CUDART_INF_F, -CUDART_INF_F);
    float4 sm = make_float4(0.f, 0.f, 0.f, 0.f);

    #pragma unroll 1
    for (int ch = 0; ch < CR / 8; ++ch) {       // 8 chunks of 8 channels
        float s[8];
        #pragma unroll
        for (int j = 0; j < 8; ++j) {
            float4 v = xp[(ch * 8 + j) * (HW / 4)];
            mx.x = fmaxf(mx.x, v.x); mx.y = fmaxf(mx.y, v.y);
            mx.z = fmaxf(mx.z, v.z); mx.w = fmaxf(mx.w, v.w);
            sm.x += v.x; sm.y += v.y; sm.z += v.z; sm.w += v.w;
            s[j] = (v.x + v.y) + (v.z + v.w);
        }
        float (*sb)[K1T] = sbuf[ch & 1];
        #pragma unroll
        for (int j = 0; j < 8; ++j) sb[j][tid] = s[j];
        __syncthreads();
        // warp w reduces channel (chunk*8 + w): 256 values, stride-32 = conflict-free
        float r = 0.f;
        #pragma unroll
        for (int k = 0; k < 8; ++k) r += sb[warp][lane + 32 * k];
        r += __shfl_xor_sync(0xffffffffu, r, 16);
        r += __shfl_xor_sync(0xffffffffu, r, 8);
        r += __shfl_xor_sync(0xffffffffu, r, 4);
        r += __shfl_xor_sync(0xffffffffu, r, 2);
        r += __shfl_xor_sync(0xffffffffu, r, 1);
        if (lane == 0) {
            int c = cr * CR + ch * 8 + warp;
            g_cpart[(b * NHWT + ht) * C + c] = r;   // unique writer per slot
        }
    }

    const int o = (b * HW + ht * HWT) / 4 + tid;
    g_pmax[cr][o] = mx;
    g_psum[cr][o] = sm;
}

// =====================================================================
// k2: finish per-(b,c) mean, 5-tap conv1d along c (pad 2), sigmoid.
// =====================================================================
__global__ __launch_bounds__(C) void k2_chw(const float* __restrict__ w1d)
{
    const int b = blockIdx.x;
    const int c = threadIdx.x;

    float acc = 0.f;
    #pragma unroll
    for (int ht = 0; ht < NHWT; ++ht)
        acc += g_cpart[(b * NHWT + ht) * C + c];

    __shared__ float mean[C];
    mean[c] = acc * (1.0f / (float)HW);
    __syncthreads();

    float y = 0.f;
    #pragma unroll
    for (int k = 0; k < 5; ++k) {
        int cc = c - 2 + k;
        float m = (cc >= 0 && cc < C) ? mean[cc] : 0.f;
        y += w1d[k] * m;
    }
    g_chw[b * C + c] = 1.0f / (1.0f + expf(-y));
}

// =====================================================================
// k3: spatial attention. Combines the 4 c-range pool partials during the
//     smem load, then 7x7/2ch conv (pad 3) + bias + sigmoid.
// =====================================================================
#define K3_ROWS 16
__global__ __launch_bounds__(256) void k3_sp(const float* __restrict__ w2d,
                                             const float* __restrict__ bias)
{
    const int b   = blockIdx.x >> 2;
    const int rt  = blockIdx.x & 3;
    const int r0  = rt * K3_ROWS;
    const int tid = threadIdx.x;

    __shared__ float smax[22][72];
    __shared__ float savg[22][72];
    __shared__ float sw[98];
    __shared__ float sb;

    for (int i = tid; i < 22 * 70; i += 256) {
        int rr = i / 70, cc = i % 70;
        int gr = r0 - 3 + rr, gc = cc - 3;
        float mv = 0.f, av = 0.f;
        if (gr >= 0 && gr < W64 && gc >= 0 && gc < W64) {
            int idx = b * HW + gr * W64 + gc;
            mv = -CUDART_INF_F;
            #pragma unroll
            for (int cr = 0; cr < NCR; ++cr) {
                mv = fmaxf(mv, ((const float*)g_pmax[cr])[idx]);
                av += ((const float*)g_psum[cr])[idx];
            }
            av *= (1.0f / (float)C);
        }
        smax[rr][cc] = mv;
        savg[rr][cc] = av;
    }
    if (tid < 98) sw[tid] = w2d[tid];
    if (tid == 0) sb = bias[0];
    __syncthreads();

    float* __restrict__ sp = (float*)g_sp4;
    #pragma unroll
    for (int k = 0; k < 4; ++k) {
        int oi   = tid + k * 256;
        int orow = oi >> 6;
        int ocol = oi & 63;
        float acc = sb;
        #pragma unroll
        for (int kh = 0; kh < 7; ++kh) {
            #pragma unroll
            for (int kw = 0; kw < 7; ++kw) {
                acc += sw[kh * 7 + kw]      * smax[orow + kh][ocol + kw];
                acc += sw[49 + kh * 7 + kw] * savg[orow + kh][ocol + kw];
            }
        }
        sp[b * HW + (r0 + orow) * W64 + ocol] = 1.0f / (1.0f + expf(-acc));
    }
}

// =====================================================================
// k4: out = x * (chw[b,c] + sp[b,hw] + 1)
//     Reversed traversal: k1 streamed x front-to-back, so the TAIL of x
//     is L2-resident — read it first. Output stores use evict-first.
// =====================================================================
#define TOTAL4 (B * C * HW / 4)
__global__ __launch_bounds__(256) void k4_scale(const float4* __restrict__ x4,
                                                float4* __restrict__ out4)
{
    const int i4  = (TOTAL4 - 1) - (blockIdx.x * 256 + threadIdx.x);
    const int hw4 = i4 & 1023;         // HW/4 = 1024
    const int bc  = i4 >> 10;
    const int b   = bc >> 8;

    const float  cw = g_chw[bc] + 1.0f;
    const float4 sp = g_sp4[b * 1024 + hw4];
    const float4 v  = x4[i4];

    float4 o;
    o.x = v.x * (cw + sp.x);
    o.y = v.y * (cw + sp.y);
    o.z = v.z * (cw + sp.z);
    o.w = v.w * (cw + sp.w);
    __stcs(&out4[i4], o);
}

// =====================================================================
extern "C" void kernel_launch(void* const* d_in, const int* in_sizes, int n_in,
                              void* d_out, int out_size)
{
    const float* x    = (const float*)d_in[0];  // [32,256,64,64]
    const float* w1d  = (const float*)d_in[1];  // [1,1,5]
    const float* w2d  = (const float*)d_in[2];  // [1,2,7,7]
    const float* bias = (const float*)d_in[3];  // [1]
    float* out = (float*)d_out;

    dim3 g1(NCR, NHWT, B);
    k1_reduce<<<g1, K1T>>>(x);
    k2_chw<<<B, C>>>(w1d);
    k3_sp<<<B * 4, 256>>>(w2d, bias);
    k4_scale<<<TOTAL4 / 256, 256>>>((const float4*)x, (float4*)out);
}

// round 3
// speedup vs baseline: 1.8173x; 1.1122x over previous
#include <cuda_runtime.h>
#include <math_constants.h>

// x [B=32, C=256, H=64, W=64] fp32
#define B    32
#define C    256
#define HW   4096
#define W64  64

// ---- k1 tiling ----
#define K1T    128             // threads/block
#define HWT    512             // hw floats per block tile (128 float4)
#define NHWT   (HW / HWT)      // 8
#define CR     64              // channels per block
#define NCR    (C / CR)        // 4
#define CHUNK  4
#define NCHUNK (CR / CHUNK)    // 16

// ---- scratch (device globals; allocation-free) ----
__device__ float  g_cpart[B * NHWT * C];     // per-(b,c,hw-tile) partial sums
__device__ float4 g_pmax[NCR][B * HW / 4];   // per-c-range max partials
__device__ float4 g_psum[NCR][B * HW / 4];   // per-c-range sum partials
__device__ float  g_chw[B * C];              // channel weight
__device__ float4 g_sp4[B * HW / 4];         // spatial weight

// =====================================================================
// k1: single sweep over x. block=(cr,ht,b), 1024 CTAs, 8/SM resident.
// Register-prefetched 4-channel chunks; smem transpose for per-c sums.
// =====================================================================
__global__ __launch_bounds__(K1T) void k1_reduce(const float* __restrict__ x)
{
    const int cr   = blockIdx.x;
    const int ht   = blockIdx.y;
    const int b    = blockIdx.z;
    const int tid  = threadIdx.x;
    const int warp = tid >> 5;
    const int lane = tid & 31;

    __shared__ float sbuf[2][CHUNK][K1T];

    const float4* __restrict__ xp =
        (const float4*)x + ((long)(b * C + cr * CR) * HW + ht * HWT) / 4 + tid;

    float4 mx = make_float4(-CUDART_INF_F, -CUDART_INF_F, -CUDART_INF_F, -CUDART_INF_F);
    float4 sm = make_float4(0.f, 0.f, 0.f, 0.f);

    float4 p[CHUNK];
    #pragma unroll
    for (int j = 0; j < CHUNK; ++j) p[j] = xp[j * (HW / 4)];

    #pragma unroll 2
    for (int ch = 0; ch < NCHUNK; ++ch) {
        float4 v[CHUNK];
        #pragma unroll
        for (int j = 0; j < CHUNK; ++j) v[j] = p[j];

        // stage per-thread channel sums, then kick off next chunk's loads
        float (*sb)[K1T] = sbuf[ch & 1];
        #pragma unroll
        for (int j = 0; j < CHUNK; ++j)
            sb[j][tid] = (v[j].x + v[j].y) + (v[j].z + v[j].w);

        if (ch + 1 < NCHUNK) {
            #pragma unroll
            for (int j = 0; j < CHUNK; ++j)
                p[j] = xp[((ch + 1) * CHUNK + j) * (HW / 4)];
        }

        #pragma unroll
        for (int j = 0; j < CHUNK; ++j) {
            mx.x = fmaxf(mx.x, v[j].x); mx.y = fmaxf(mx.y, v[j].y);
            mx.z = fmaxf(mx.z, v[j].z); mx.w = fmaxf(mx.w, v[j].w);
            sm.x += v[j].x; sm.y += v[j].y; sm.z += v[j].z; sm.w += v[j].w;
        }

        __syncthreads();
        // warp w reduces channel ch*4+w over all 128 threads (stride-32: conflict-free)
        float r = (sb[warp][lane]      + sb[warp][lane + 32])
                + (sb[warp][lane + 64] + sb[warp][lane + 96]);
        r += __shfl_xor_sync(0xffffffffu, r, 16);
        r += __shfl_xor_sync(0xffffffffu, r, 8);
        r += __shfl_xor_sync(0xffffffffu, r, 4);
        r += __shfl_xor_sync(0xffffffffu, r, 2);
        r += __shfl_xor_sync(0xffffffffu, r, 1);
        if (lane == 0)
            g_cpart[(b * NHWT + ht) * C + cr * CR + ch * CHUNK + warp] = r;
    }

    const int o = b * (HW / 4) + ht * (HWT / 4) + tid;
    g_pmax[cr][o] = mx;
    g_psum[cr][o] = sm;
}

// =====================================================================
// k23: fused channel-weight (blocks 0..31) and spatial-weight (32..159).
// =====================================================================
#define SMAX_OFF 0
#define SAVG_OFF (22 * 72)
#define SW_OFF   (2 * 22 * 72)
#define SB_OFF   (SW_OFF + 98)

__global__ __launch_bounds__(256) void k23(const float* __restrict__ w1d,
                                           const float* __restrict__ w2d,
                                           const float* __restrict__ bias)
{
    __shared__ float sbig[SB_OFF + 1];
    const int tid = threadIdx.x;

    if (blockIdx.x < B) {
        // ---- channel weight: mean -> conv1d(5, pad 2) -> sigmoid ----
        const int b = blockIdx.x;
        const int c = tid;
        float acc = 0.f;
        #pragma unroll
        for (int ht = 0; ht < NHWT; ++ht)
            acc += g_cpart[(b * NHWT + ht) * C + c];
        sbig[c] = acc * (1.0f / (float)HW);
        __syncthreads();
        float y = 0.f;
        #pragma unroll
        for (int k = 0; k < 5; ++k) {
            int cc = c - 2 + k;
            float m = (cc >= 0 && cc < C) ? sbig[cc] : 0.f;
            y += w1d[k] * m;
        }
        g_chw[b * C + c] = 1.0f / (1.0f + expf(-y));
    } else {
        // ---- spatial weight: pools -> conv2d(7x7, pad 3) -> sigmoid ----
        const int idx = blockIdx.x - B;
        const int b   = idx >> 2;
        const int r0  = (idx & 3) * 16;

        float* smax = sbig + SMAX_OFF;   // [22][72]
        float* savg = sbig + SAVG_OFF;   // [22][72]
        float* sw   = sbig + SW_OFF;     // [98]

        for (int i = tid; i < 22 * 70; i += 256) {
            int rr = i / 70, cc = i % 70;
            int gr = r0 - 3 + rr, gc = cc - 3;
            float mv = 0.f, av = 0.f;
            if (gr >= 0 && gr < W64 && gc >= 0 && gc < W64) {
                int gi = b * HW + gr * W64 + gc;
                mv = -CUDART_INF_F;
                #pragma unroll
                for (int r = 0; r < NCR; ++r) {
                    mv = fmaxf(mv, ((const float*)g_pmax[r])[gi]);
                    av += ((const float*)g_psum[r])[gi];
                }
                av *= (1.0f / (float)C);
            }
            smax[rr * 72 + cc] = mv;
            savg[rr * 72 + cc] = av;
        }
        if (tid < 98) sw[tid] = w2d[tid];
        if (tid == 0) sbig[SB_OFF] = bias[0];
        __syncthreads();

        float* __restrict__ sp = (float*)g_sp4;
        #pragma unroll
        for (int k = 0; k < 4; ++k) {
            int oi   = tid + k * 256;
            int orow = oi >> 6;
            int ocol = oi & 63;
            float acc = sbig[SB_OFF];
            #pragma unroll
            for (int kh = 0; kh < 7; ++kh) {
                #pragma unroll
                for (int kw = 0; kw < 7; ++kw) {
                    acc += sw[kh * 7 + kw]      * smax[(orow + kh) * 72 + ocol + kw];
                    acc += sw[49 + kh * 7 + kw] * savg[(orow + kh) * 72 + ocol + kw];
                }
            }
            sp[b * HW + (r0 + orow) * W64 + ocol] = 1.0f / (1.0f + expf(-acc));
        }
    }
}

// =====================================================================
// k4: out = x * (chw[b,c] + sp[b,hw] + 1), reversed traversal + stcs.
// =====================================================================
#define TOTAL4 (B * C * HW / 4)
__global__ __launch_bounds__(256) void k4_scale(const float4* __restrict__ x4,
                                                float4* __restrict__ out4)
{
    const int i4  = (TOTAL4 - 1) - (blockIdx.x * 256 + threadIdx.x);
    const int hw4 = i4 & 1023;
    const int bc  = i4 >> 10;
    const int b   = bc >> 8;

    const float  cw = g_chw[bc] + 1.0f;
    const float4 sp = g_sp4[b * 1024 + hw4];
    const float4 v  = x4[i4];

    float4 o;
    o.x = v.x * (cw + sp.x);
    o.y = v.y * (cw + sp.y);
    o.z = v.z * (cw + sp.z);
    o.w = v.w * (cw + sp.w);
    __stcs(&out4[i4], o);
}

// =====================================================================
extern "C" void kernel_launch(void* const* d_in, const int* in_sizes, int n_in,
                              void* d_out, int out_size)
{
    const float* x    = (const float*)d_in[0];  // [32,256,64,64]
    const float* w1d  = (const float*)d_in[1];  // [1,1,5]
    const float* w2d  = (const float*)d_in[2];  // [1,2,7,7]
    const float* bias = (const float*)d_in[3];  // [1]
    float* out = (float*)d_out;

    dim3 g1(NCR, NHWT, B);
    k1_reduce<<<g1, K1T>>>(x);
    k23<<<B + B * 4, 256>>>(w1d, w2d, bias);
    k4_scale<<<TOTAL4 / 256, 256>>>((const float4*)x, (float4*)out);
}